// round 4
// baseline (speedup 1.0000x reference)
#include <cuda_runtime.h>
#include <cstdint>

// B=4096, A=128, RF=K=128, F=128, fp32. out = row_mask * relu(resid @ w + node)
#define A_DIM     128
#define F_DIM     128
#define K_DIM     128
#define TILE_ROWS 64
#define KC        16
#define RPAD      (2*TILE_ROWS + 4)   // 132 floats/row: 528B, 16B-aligned rows

__device__ __forceinline__ unsigned long long ffma2(unsigned long long a,
                                                    unsigned long long b,
                                                    unsigned long long c) {
    unsigned long long d;
    asm("fma.rn.f32x2 %0, %1, %2, %3;" : "=l"(d) : "l"(a), "l"(b), "l"(c));
    return d;
}

__global__ __launch_bounds__(256)
void blockend_kernel(const float* __restrict__ node,
                     const float* __restrict__ resid,
                     const float* __restrict__ w,
                     const int*   __restrict__ mol_i32,
                     float* __restrict__ out)
{
    const int b    = blockIdx.x;
    const int row0 = blockIdx.y * TILE_ROWS;
    const int t    = threadIdx.x;

    // mol_slice layout detection: int64 -> i32 view [M,0,128,0,...]; int32 -> [M,128,...]
    const bool is_i64 = (mol_i32[1] == 0);
    const int  M      = is_i64 ? mol_i32[4 * b] : mol_i32[2 * b];

    float* outp = out + ((size_t)b * A_DIM + row0) * F_DIM;

    // ---- fully masked tile: zero fill ----
    if (row0 >= M) {
        float4 z = make_float4(0.f, 0.f, 0.f, 0.f);
        float4* o4 = (float4*)outp;
        #pragma unroll
        for (int i = 0; i < (TILE_ROWS * F_DIM / 4) / 256; i++)
            o4[t + i * 256] = z;
        return;
    }

    __shared__ float ws[KC][F_DIM];     // ws[kk][f] = w[k0+kk][f]
    __shared__ float rrep[KC][RPAD];    // each residual value stored replicated (v,v)

    const float* residp = resid + ((size_t)b * A_DIM + row0) * K_DIM;

    const int tx = t & 31;    // cols tx*4 .. tx*4+3
    const int ty = t >> 5;    // rows ty*8 .. ty*8+7

    unsigned long long acc[8][2];
    #pragma unroll
    for (int i = 0; i < 8; i++) { acc[i][0] = 0ULL; acc[i][1] = 0ULL; }

    const int lrow = t >> 2;          // 0..63 (4 threads per row)
    const int slot = t & 3;           // 0..3  -> kk group slot*4

    for (int k0 = 0; k0 < K_DIM; k0 += KC) {
        if (k0) __syncthreads();

        // stage W chunk: 16 x 128 floats = 512 float4, 2 per thread
        {
            const float4* wsrc = (const float4*)(w + (size_t)k0 * F_DIM);
            float4* wdst = (float4*)&ws[0][0];
            #pragma unroll
            for (int i = 0; i < 2; i++)
                wdst[t + i * 256] = wsrc[t + i * 256];
        }
        // stage residual chunk replicated: rrep[kk][2r]=rrep[kk][2r+1]=resid[row0+r][k0+kk]
        {
            const float4* rsrc = (const float4*)(residp + (size_t)lrow * K_DIM + k0);
            float4 v0 = rsrc[slot];            // kk = slot*4 .. slot*4+3
            const int kb = slot * 4;
            float2 p;
            p.x = p.y = v0.x; *(float2*)&rrep[kb + 0][2 * lrow] = p;
            p.x = p.y = v0.y; *(float2*)&rrep[kb + 1][2 * lrow] = p;
            p.x = p.y = v0.z; *(float2*)&rrep[kb + 2][2 * lrow] = p;
            p.x = p.y = v0.w; *(float2*)&rrep[kb + 3][2 * lrow] = p;
        }
        __syncthreads();

        #pragma unroll
        for (int kk = 0; kk < KC; kk++) {
            ulonglong2 bb = *(const ulonglong2*)&ws[kk][tx * 4];        // (f0,f1),(f2,f3)
            const ulonglong2* ap = (const ulonglong2*)&rrep[kk][2 * (ty * 8)];
            ulonglong2 a01 = ap[0];   // rows +0,+1 (broadcast across warp)
            ulonglong2 a23 = ap[1];
            ulonglong2 a45 = ap[2];
            ulonglong2 a67 = ap[3];
            acc[0][0] = ffma2(a01.x, bb.x, acc[0][0]);
            acc[0][1] = ffma2(a01.x, bb.y, acc[0][1]);
            acc[1][0] = ffma2(a01.y, bb.x, acc[1][0]);
            acc[1][1] = ffma2(a01.y, bb.y, acc[1][1]);
            acc[2][0] = ffma2(a23.x, bb.x, acc[2][0]);
            acc[2][1] = ffma2(a23.x, bb.y, acc[2][1]);
            acc[3][0] = ffma2(a23.y, bb.x, acc[3][0]);
            acc[3][1] = ffma2(a23.y, bb.y, acc[3][1]);
            acc[4][0] = ffma2(a45.x, bb.x, acc[4][0]);
            acc[4][1] = ffma2(a45.x, bb.y, acc[4][1]);
            acc[5][0] = ffma2(a45.y, bb.x, acc[5][0]);
            acc[5][1] = ffma2(a45.y, bb.y, acc[5][1]);
            acc[6][0] = ffma2(a67.x, bb.x, acc[6][0]);
            acc[6][1] = ffma2(a67.x, bb.y, acc[6][1]);
            acc[7][0] = ffma2(a67.y, bb.x, acc[7][0]);
            acc[7][1] = ffma2(a67.y, bb.y, acc[7][1]);
        }
    }

    // ---- epilogue: + node, relu, row mask, store ----
    const float* nodep = node + ((size_t)b * A_DIM + row0) * F_DIM;
    #pragma unroll
    for (int i = 0; i < 8; i++) {
        int r = ty * 8 + i;
        float4 o;
        if (row0 + r < M) {
            float4 nv = *(const float4*)(nodep + (size_t)r * F_DIM + tx * 4);
            float2 p0 = *(float2*)&acc[i][0];
            float2 p1 = *(float2*)&acc[i][1];
            o.x = fmaxf(p0.x + nv.x, 0.f);
            o.y = fmaxf(p0.y + nv.y, 0.f);
            o.z = fmaxf(p1.x + nv.z, 0.f);
            o.w = fmaxf(p1.y + nv.w, 0.f);
        } else {
            o = make_float4(0.f, 0.f, 0.f, 0.f);
        }
        *(float4*)(outp + (size_t)r * F_DIM + tx * 4) = o;
    }
}

extern "C" void kernel_launch(void* const* d_in, const int* in_sizes, int n_in,
                              void* d_out, int out_size) {
    // Size-based input identification (robust to metadata ordering).
    const float* node = nullptr;
    const float* res  = nullptr;
    const void*  wptr = nullptr;
    const void*  mptr = nullptr;

    for (int i = 0; i < n_in; i++) {
        if (in_sizes[i] >= (1 << 20)) {
            if (!node) node = (const float*)d_in[i];
            else if (!res) res = (const float*)d_in[i];
        }
    }
    for (int i = 0; i < n_in; i++) {
        if (in_sizes[i] < (1 << 20)) {
            if (!wptr && in_sizes[i] == F_DIM * K_DIM) { wptr = d_in[i]; continue; }
            if (!mptr && d_in[i] != wptr) mptr = d_in[i];
        }
    }
    if (!node) node = (const float*)d_in[0];
    if (!res)  res  = (const float*)d_in[1];
    if (!wptr) wptr = d_in[2];
    if (!mptr) mptr = d_in[3];

    float* out = (float*)d_out;
    int B = 0;
    for (int i = 0; i < n_in; i++)
        if (in_sizes[i] >= (1 << 20)) { B = in_sizes[i] / (A_DIM * F_DIM); break; }
    if (!B) B = 4096;

    dim3 grid(B, A_DIM / TILE_ROWS);
    blockend_kernel<<<grid, 256>>>(node, res, (const float*)wptr,
                                   (const int*)mptr, out);
}